// round 1
// baseline (speedup 1.0000x reference)
#include <cuda_runtime.h>
#include <math.h>

// ---------------- problem constants ----------------
#define BB    128
#define SS    256
#define LLQ   10
#define TAGS  32
#define STARTT 30
#define ENDT   31
#define WDIM  100
#define CDIM  30
#define FILT  30
#define HH    100
#define LSTM_IN 130
#define G4    400
#define NEGV  (-10000.0f)

// ---------------- scratch (static device globals; no allocs allowed) ----------------
__device__ float g_x [BB*SS*LSTM_IN];          // concat(word_emb, char_feat)   17 MB
__device__ float g_xw[2][BB*SS*G4];            // x @ wih^T + b, per dir       105 MB
__device__ float g_h [2][BB*SS*HH];            // lstm hidden per dir           26 MB
__device__ float g_em[BB*SS*TAGS];             // emission                       4 MB
__device__ float g_res[BB];                    // per-batch (score_y - total)

// ---------------- helpers ----------------
__device__ __forceinline__ float sigf(float x) {
    return __fdividef(1.0f, 1.0f + __expf(-x));
}
__device__ __forceinline__ float tanhf_fast(float x) {
    float e = __expf(-2.0f * fabsf(x));       // e in (0,1], no overflow
    float t = __fdividef(1.0f - e, 1.0f + e);
    return copysignf(t, x);
}

// ---------------- K1: word-emb gather + char CNN ----------------
// One block per token (B*S blocks, 128 threads).
// conv: input (1, L=10, CDIM=30) padded (2,2) on L -> 14 rows, kernel (3,30) -> 12x1 out.
__global__ void k_embed(const float* __restrict__ word_emb,
                        const float* __restrict__ char_emb,
                        const float* __restrict__ conv_w,
                        const float* __restrict__ conv_b,
                        const int*   __restrict__ word_x,
                        const int*   __restrict__ char_x)
{
    int token = blockIdx.x;
    int tid = threadIdx.x;
    __shared__ float ce[14*CDIM];   // padded char embeddings
    __shared__ float cmax[FILT*4];

    const int* cx = char_x + token*LLQ;
    for (int i = tid; i < 14*CDIM; i += 128) {
        int pos = i / CDIM, d = i % CDIM;
        int q = pos - 2;
        float v = 0.0f;
        if (q >= 0 && q < LLQ) {
            int c = cx[q];
            v = char_emb[c*CDIM + d];
        }
        ce[i] = v;
    }
    int w = word_x[token];
    if (tid < WDIM) g_x[token*LSTM_IN + tid] = word_emb[(size_t)w*WDIM + tid];
    __syncthreads();

    if (tid < 120) {
        int f  = tid >> 2;
        int pq = tid & 3;
        const float* wf = conv_w + f*90;   // (f,0,k,d): f*90 + k*30 + d
        float m = -1e30f;
        for (int p = pq*3; p < pq*3 + 3; p++) {
            float s = 0.0f;
            #pragma unroll
            for (int k = 0; k < 3; k++)
                #pragma unroll
                for (int d = 0; d < CDIM; d++)
                    s += ce[(p+k)*CDIM + d] * wf[k*CDIM + d];
            m = fmaxf(m, s);
        }
        cmax[f*4 + pq] = m;
    }
    __syncthreads();
    if (tid < FILT) {
        float m = fmaxf(fmaxf(cmax[tid*4+0], cmax[tid*4+1]),
                        fmaxf(cmax[tid*4+2], cmax[tid*4+3]));
        g_x[token*LSTM_IN + WDIM + tid] = m + conv_b[tid];
    }
}

// ---------------- K2: xw = x(32768,130) @ wih^T(130,400) + (bih+bhh) ----------------
// 64x64 tile, BK=16, 256 threads, 4x4 microtile. grid (512, 7, 2).
__global__ void k_xw(const float* __restrict__ wih_f, const float* __restrict__ bih_f, const float* __restrict__ bhh_f,
                     const float* __restrict__ wih_b, const float* __restrict__ bih_b, const float* __restrict__ bhh_b)
{
    int dir = blockIdx.z;
    const float* wih = dir ? wih_b : wih_f;
    const float* bih = dir ? bih_b : bih_f;
    const float* bhh = dir ? bhh_b : bhh_f;
    float* outp = g_xw[dir];

    __shared__ float As[16*68];
    __shared__ float Bs[16*68];

    int m0 = blockIdx.x * 64;
    int n0 = blockIdx.y * 64;
    int tid = threadIdx.x;
    int lr = tid >> 2;          // 0..63 (row within tile)
    int lk = (tid & 3) * 4;     // 0,4,8,12
    int tm = (tid & 15) * 4;
    int tn = (tid >> 4) * 4;

    float acc[4][4] = {};

    for (int k0 = 0; k0 < 144; k0 += 16) {
        #pragma unroll
        for (int i = 0; i < 4; i++) {
            int k = k0 + lk + i;
            As[(lk+i)*68 + lr] = (k < LSTM_IN) ? g_x[(size_t)(m0+lr)*LSTM_IN + k] : 0.0f;
            Bs[(lk+i)*68 + lr] = (k < LSTM_IN && (n0+lr) < G4) ? wih[(size_t)(n0+lr)*LSTM_IN + k] : 0.0f;
        }
        __syncthreads();
        #pragma unroll
        for (int kk = 0; kk < 16; kk++) {
            float4 a  = *(const float4*)&As[kk*68 + tm];
            float4 bv = *(const float4*)&Bs[kk*68 + tn];
            acc[0][0] += a.x*bv.x; acc[0][1] += a.x*bv.y; acc[0][2] += a.x*bv.z; acc[0][3] += a.x*bv.w;
            acc[1][0] += a.y*bv.x; acc[1][1] += a.y*bv.y; acc[1][2] += a.y*bv.z; acc[1][3] += a.y*bv.w;
            acc[2][0] += a.z*bv.x; acc[2][1] += a.z*bv.y; acc[2][2] += a.z*bv.z; acc[2][3] += a.z*bv.w;
            acc[3][0] += a.w*bv.x; acc[3][1] += a.w*bv.y; acc[3][2] += a.w*bv.z; acc[3][3] += a.w*bv.w;
        }
        __syncthreads();
    }

    #pragma unroll
    for (int i = 0; i < 4; i++) {
        int m = m0 + tm + i;
        #pragma unroll
        for (int jx = 0; jx < 4; jx++) {
            int n = n0 + tn + jx;
            if (n < G4)
                outp[(size_t)m*G4 + n] = acc[i][jx] + bih[n] + bhh[n];
        }
    }
}

// ---------------- K3: LSTM recurrence ----------------
// 128 blocks: dir = blk/64, batch pair = (blk%64)*2. 200 threads.
// Thread t owns gate rows (2t, 2t+1) for both batch rows (4 accumulators).
// whh stored k-major in shared: whh_s[k*400 + row] -> conflict-free float2 reads.
#define LSTM_SMEM_FLOATS (40000 + 104 + 104 + 800)
#define LSTM_SMEM_BYTES  (LSTM_SMEM_FLOATS * 4)

__global__ void k_lstm(const float* __restrict__ whh_f, const float* __restrict__ whh_b)
{
    extern __shared__ float sm[];
    float* whh_s = sm;            // 40000 floats (k-major [100][400])
    float* h0    = sm + 40000;    // 100 (+4 pad), 16B aligned
    float* h1    = sm + 40104;    // 100 (+4 pad), 16B aligned
    float* gate  = sm + 40208;    // 2 * 400

    int t   = threadIdx.x;        // 0..199
    int dir = blockIdx.x >> 6;
    int b0  = (blockIdx.x & 63) * 2;

    const float* whh = dir ? whh_b : whh_f;
    const float* xw  = g_xw[dir];
    float* hout = g_h[dir];

    for (int idx = t; idx < 40000; idx += 200) {
        int r = idx / HH, k = idx % HH;
        whh_s[k*G4 + r] = whh[idx];
    }
    if (t < HH) { h0[t] = 0.0f; h1[t] = 0.0f; }
    float c_reg = 0.0f;
    int r_act = t / HH;           // 0 or 1 (batch row for activation phase)
    int j_act = t - r_act*HH;     // 0..99
    __syncthreads();

    int g = 2*t;
    const float4* h0f = (const float4*)h0;
    const float4* h1f = (const float4*)h1;

    for (int step = 0; step < SS; step++) {
        int sidx = dir ? (SS-1-step) : step;
        float2 x0 = *(const float2*)(xw + ((size_t)b0    *SS + sidx)*G4 + g);
        float2 x1 = *(const float2*)(xw + ((size_t)(b0+1)*SS + sidx)*G4 + g);
        float a00 = x0.x, a10 = x0.y, a01 = x1.x, a11 = x1.y;

        #pragma unroll
        for (int k4 = 0; k4 < 25; k4++) {
            float4 hv0 = h0f[k4];
            float4 hv1 = h1f[k4];
            float2 w0 = *(const float2*)&whh_s[(k4*4+0)*G4 + g];
            a00 += w0.x*hv0.x; a10 += w0.y*hv0.x; a01 += w0.x*hv1.x; a11 += w0.y*hv1.x;
            float2 w1 = *(const float2*)&whh_s[(k4*4+1)*G4 + g];
            a00 += w1.x*hv0.y; a10 += w1.y*hv0.y; a01 += w1.x*hv1.y; a11 += w1.y*hv1.y;
            float2 w2 = *(const float2*)&whh_s[(k4*4+2)*G4 + g];
            a00 += w2.x*hv0.z; a10 += w2.y*hv0.z; a01 += w2.x*hv1.z; a11 += w2.y*hv1.z;
            float2 w3 = *(const float2*)&whh_s[(k4*4+3)*G4 + g];
            a00 += w3.x*hv0.w; a10 += w3.y*hv0.w; a01 += w3.x*hv1.w; a11 += w3.y*hv1.w;
        }
        *(float2*)&gate[g]       = make_float2(a00, a10);
        *(float2*)&gate[G4 + g]  = make_float2(a01, a11);
        __syncthreads();

        {
            const float* gs = gate + r_act*G4;
            float gi = gs[j_act], gf = gs[HH + j_act], gg = gs[2*HH + j_act], go = gs[3*HH + j_act];
            float si = sigf(gi), sf = sigf(gf), so = sigf(go);
            c_reg = sf*c_reg + si*tanhf_fast(gg);
            float h = so*tanhf_fast(c_reg);
            ((r_act == 0) ? h0 : h1)[j_act] = h;
            hout[((size_t)(b0 + r_act)*SS + sidx)*HH + j_act] = h;
        }
        __syncthreads();
    }
}

// ---------------- K4: emission = [h_f | h_b] @ proj_w^T + proj_b ----------------
// 2048 blocks x 128 threads; 16 rows per block; proj_w transposed in shared.
__global__ void k_emission(const float* __restrict__ proj_w, const float* __restrict__ proj_b)
{
    __shared__ float pwsT[200*TAGS];   // [k][tag]
    __shared__ float hs[16*200];       // [row][k]  (k<100 = h_f, k>=100 = h_b)
    int tid = threadIdx.x;
    int m0 = blockIdx.x * 16;

    for (int idx = tid; idx < TAGS*200; idx += 128) {
        int tag = idx / 200, k = idx % 200;
        pwsT[k*TAGS + tag] = proj_w[idx];
    }
    for (int idx = tid; idx < 16*200; idx += 128) {
        int r = idx / 200, k = idx % 200;
        hs[idx] = (k < HH) ? g_h[0][(size_t)(m0+r)*HH + k]
                           : g_h[1][(size_t)(m0+r)*HH + (k-HH)];
    }
    __syncthreads();

    int tag = tid & 31;
    int yg  = tid >> 5;                 // 0..3 -> rows yg*4..yg*4+3
    float acc0 = 0.f, acc1 = 0.f, acc2 = 0.f, acc3 = 0.f;
    const float* h0r = hs + (yg*4+0)*200;
    const float* h1r = hs + (yg*4+1)*200;
    const float* h2r = hs + (yg*4+2)*200;
    const float* h3r = hs + (yg*4+3)*200;
    #pragma unroll 8
    for (int k = 0; k < 200; k++) {
        float w = pwsT[k*TAGS + tag];
        acc0 += h0r[k]*w; acc1 += h1r[k]*w; acc2 += h2r[k]*w; acc3 += h3r[k]*w;
    }
    float pb = proj_b[tag];
    g_em[(size_t)(m0+yg*4+0)*TAGS + tag] = acc0 + pb;
    g_em[(size_t)(m0+yg*4+1)*TAGS + tag] = acc1 + pb;
    g_em[(size_t)(m0+yg*4+2)*TAGS + tag] = acc2 + pb;
    g_em[(size_t)(m0+yg*4+3)*TAGS + tag] = acc3 + pb;
}

// ---------------- K5: CRF forward + gold score, one warp per batch row ----------------
__global__ void k_crf(const float* __restrict__ trans,
                      const int* __restrict__ y, const int* __restrict__ mask)
{
    int b = blockIdx.x;
    int j = threadIdx.x;    // tag 0..31

    float tr[32];
    #pragma unroll
    for (int i = 0; i < 32; i++) tr[i] = trans[i*TAGS + j];

    float la = (j == STARTT) ? 0.0f : NEGV;
    const float* em = g_em + (size_t)b*SS*TAGS;
    const int* mk = mask + b*SS;

    for (int s = 0; s < SS; s++) {
        float e = em[s*TAGS + j];
        float v[32];
        float m = -1e30f;
        #pragma unroll
        for (int i = 0; i < 32; i++) {
            float l = __shfl_sync(0xffffffffu, la, i);
            v[i] = l + tr[i];
            m = fmaxf(m, v[i]);
        }
        float sum = 0.0f;
        #pragma unroll
        for (int i = 0; i < 32; i++) sum += __expf(v[i] - m);
        float la2 = e + m + __logf(sum);
        la = mk[s] ? la2 : la;
    }
    la += trans[j*TAGS + ENDT];

    float mv = la;
    #pragma unroll
    for (int o = 16; o > 0; o >>= 1) mv = fmaxf(mv, __shfl_xor_sync(0xffffffffu, mv, o));
    float ex = __expf(la - mv);
    #pragma unroll
    for (int o = 16; o > 0; o >>= 1) ex += __shfl_xor_sync(0xffffffffu, ex, o);
    float total = mv + __logf(ex);

    // gold score
    const int* yb = y + b*SS;
    float sc = 0.0f;
    for (int s = j; s < SS; s += 32) {
        int cur  = yb[s];
        int prev = s ? yb[s-1] : STARTT;
        float p = em[s*TAGS + cur];
        float tt = trans[prev*TAGS + cur];
        sc += (p + tt) * (float)mk[s];
    }
    #pragma unroll
    for (int o = 16; o > 0; o >>= 1) sc += __shfl_xor_sync(0xffffffffu, sc, o);

    if (j == 0) {
        sc += trans[yb[SS-1]*TAGS + ENDT];
        g_res[b] = sc - total;
    }
}

// ---------------- K6: final reduction ----------------
__global__ void k_final(float* out)
{
    __shared__ float s[BB];
    int t = threadIdx.x;
    s[t] = g_res[t];
    __syncthreads();
    for (int o = 64; o > 0; o >>= 1) {
        if (t < o) s[t] += s[t+o];
        __syncthreads();
    }
    if (t == 0) out[0] = -s[0] / (float)BB;
}

// ---------------- launch ----------------
extern "C" void kernel_launch(void* const* d_in, const int* in_sizes, int n_in,
                              void* d_out, int out_size)
{
    const float* word_emb = (const float*)d_in[0];
    const float* char_emb = (const float*)d_in[1];
    const float* conv_w   = (const float*)d_in[2];
    const float* conv_b   = (const float*)d_in[3];
    const float* wih_f    = (const float*)d_in[4];
    const float* whh_f    = (const float*)d_in[5];
    const float* bih_f    = (const float*)d_in[6];
    const float* bhh_f    = (const float*)d_in[7];
    const float* wih_b    = (const float*)d_in[8];
    const float* whh_b    = (const float*)d_in[9];
    const float* bih_b    = (const float*)d_in[10];
    const float* bhh_b    = (const float*)d_in[11];
    const float* proj_w   = (const float*)d_in[12];
    const float* proj_b   = (const float*)d_in[13];
    const float* trans    = (const float*)d_in[14];
    const int*   word_x   = (const int*)d_in[15];
    const int*   char_x   = (const int*)d_in[16];
    const int*   y        = (const int*)d_in[17];
    const int*   mask     = (const int*)d_in[18];
    float* out = (float*)d_out;

    k_embed<<<BB*SS, 128>>>(word_emb, char_emb, conv_w, conv_b, word_x, char_x);

    dim3 g2(512, 7, 2);
    k_xw<<<g2, 256>>>(wih_f, bih_f, bhh_f, wih_b, bih_b, bhh_b);

    cudaFuncSetAttribute(k_lstm, cudaFuncAttributeMaxDynamicSharedMemorySize, LSTM_SMEM_BYTES);
    k_lstm<<<128, 200, LSTM_SMEM_BYTES>>>(whh_f, whh_b);

    k_emission<<<BB*SS/16, 128>>>(proj_w, proj_b);

    k_crf<<<BB, 32>>>(trans, y, mask);

    k_final<<<1, BB>>>(out);
}

// round 3
// speedup vs baseline: 1.8882x; 1.8882x over previous
#include <cuda_runtime.h>
#include <math.h>

// ---------------- problem constants ----------------
#define BB    128
#define SS    256
#define LLQ   10
#define TAGS  32
#define STARTT 30
#define ENDT   31
#define WDIM  100
#define CDIM  30
#define FILT  30
#define HH    100
#define LSTM_IN 130
#define G4    400
#define NEGV  (-10000.0f)

typedef unsigned long long ull;

// ---------------- scratch ----------------
__device__ float g_T  [100*3*FILT];            // conv table T[c][k][f]
__device__ float g_x  [BB*SS*LSTM_IN];         // concat(word_emb, char_feat)
__device__ float g_xw [2][BB*SS*G4];           // x @ wih^T + b, per dir
__device__ float g_hcat[BB*SS*2*HH];           // [token][dir*100+j]
__device__ float g_em [BB*SS*TAGS];            // emission
__device__ float g_res[BB];

// ---------------- helpers ----------------
__device__ __forceinline__ float sigf(float x) {
    return __fdividef(1.0f, 1.0f + __expf(-x));
}
__device__ __forceinline__ float tanhf_fast(float x) {
    float e = __expf(-2.0f * fabsf(x));
    float t = __fdividef(1.0f - e, 1.0f + e);
    return copysignf(t, x);
}
__device__ __forceinline__ ull ffma2(ull a, ull b, ull c) {
    ull d;
    asm("fma.rn.f32x2 %0, %1, %2, %3;" : "=l"(d) : "l"(a), "l"(b), "l"(c));
    return d;
}
__device__ __forceinline__ ull splat2(float x) {
    ull d; asm("mov.b64 %0, {%1, %1};" : "=l"(d) : "f"(x)); return d;
}
__device__ __forceinline__ float2 unpack2(ull v) {
    float2 r; asm("mov.b64 {%0, %1}, %2;" : "=f"(r.x), "=f"(r.y) : "l"(v)); return r;
}

// ---------------- K0: conv table T[c][k][f] = dot(char_emb[c], conv_w[f,k,:]) ----
__global__ void k_table(const float* __restrict__ char_emb,
                        const float* __restrict__ conv_w)
{
    __shared__ float ce[CDIM];
    int c = blockIdx.x;
    int t = threadIdx.x;       // 0..89
    if (t < CDIM) ce[t] = char_emb[c*CDIM + t];
    __syncthreads();
    int k = t / FILT, f = t % FILT;
    float s = 0.0f;
    #pragma unroll
    for (int d = 0; d < CDIM; d++) s += ce[d] * conv_w[f*90 + k*CDIM + d];
    g_T[c*90 + k*FILT + f] = s;
}

// ---------------- K1: word-emb gather + char maxpool (table lookup) ----------------
// One warp per token; 8 warps per block; T staged in shared.
__global__ void k_embed(const float* __restrict__ word_emb,
                        const float* __restrict__ conv_b,
                        const int*   __restrict__ word_x,
                        const int*   __restrict__ char_x)
{
    __shared__ float ts[9000];
    int tid = threadIdx.x;
    for (int i = tid; i < 9000; i += 256) ts[i] = g_T[i];
    __syncthreads();

    int lane = tid & 31;
    int token = blockIdx.x * 8 + (tid >> 5);

    // word part
    int w = word_x[token];
    for (int i = lane; i < WDIM; i += 32)
        g_x[(size_t)token*LSTM_IN + i] = word_emb[(size_t)w*WDIM + i];

    // char part
    int cval = (lane < LLQ) ? char_x[(size_t)token*LLQ + lane] : 0;
    int f2 = (lane < FILT) ? lane : 0;

    float best = -1e30f;
    #pragma unroll
    for (int p = 0; p < 12; p++) {
        float s = 0.0f;
        #pragma unroll
        for (int k = 0; k < 3; k++) {
            int q = p + k - 2;
            if (q >= 0 && q < LLQ) {
                int cq = __shfl_sync(0xffffffffu, cval, q);
                s += ts[cq*90 + k*FILT + f2];
            }
        }
        best = fmaxf(best, s);
    }
    if (lane < FILT)
        g_x[(size_t)token*LSTM_IN + WDIM + lane] = best + conv_b[lane];
}

// ---------------- K2: xw = x(32768,130) @ wih^T(130,400) + (bih+bhh) ----------------
// 64x64 tile, BK=16, 256 threads, FFMA2 micro 8m x 2n. grid (512, 7, 2).
__global__ void k_xw(const float* __restrict__ wih_f, const float* __restrict__ bih_f, const float* __restrict__ bhh_f,
                     const float* __restrict__ wih_b, const float* __restrict__ bih_b, const float* __restrict__ bhh_b)
{
    int dir = blockIdx.z;
    const float* wih = dir ? wih_b : wih_f;
    const float* bih = dir ? bih_b : bih_f;
    const float* bhh = dir ? bhh_b : bhh_f;
    float* outp = g_xw[dir];

    __shared__ float As[16*68];
    __shared__ float Bs[16*68];

    int m0 = blockIdx.x * 64;
    int n0 = blockIdx.y * 64;
    int tid = threadIdx.x;
    int lr = tid >> 2;
    int lk = (tid & 3) * 4;
    int mbase = (tid >> 5) * 8;
    int nb = (tid & 31) * 2;

    ull acc[4][2] = {};

    for (int k0 = 0; k0 < 144; k0 += 16) {
        #pragma unroll
        for (int i = 0; i < 4; i++) {
            int k = k0 + lk + i;
            As[(lk+i)*68 + lr] = (k < LSTM_IN) ? g_x[(size_t)(m0+lr)*LSTM_IN + k] : 0.0f;
            Bs[(lk+i)*68 + lr] = (k < LSTM_IN && (n0+lr) < G4) ? wih[(size_t)(n0+lr)*LSTM_IN + k] : 0.0f;
        }
        __syncthreads();
        #pragma unroll
        for (int kk = 0; kk < 16; kk++) {
            ulonglong2 aA = *(const ulonglong2*)&As[kk*68 + mbase];
            ulonglong2 aB = *(const ulonglong2*)&As[kk*68 + mbase + 4];
            float2 bv = *(const float2*)&Bs[kk*68 + nb];
            ull s0 = splat2(bv.x), s1 = splat2(bv.y);
            acc[0][0] = ffma2(aA.x, s0, acc[0][0]); acc[0][1] = ffma2(aA.x, s1, acc[0][1]);
            acc[1][0] = ffma2(aA.y, s0, acc[1][0]); acc[1][1] = ffma2(aA.y, s1, acc[1][1]);
            acc[2][0] = ffma2(aB.x, s0, acc[2][0]); acc[2][1] = ffma2(aB.x, s1, acc[2][1]);
            acc[3][0] = ffma2(aB.y, s0, acc[3][0]); acc[3][1] = ffma2(aB.y, s1, acc[3][1]);
        }
        __syncthreads();
    }

    int n = n0 + nb;
    if (n < G4) {
        float bn0 = bih[n] + bhh[n];
        float bn1 = bih[n+1] + bhh[n+1];
        #pragma unroll
        for (int i = 0; i < 4; i++) {
            float2 lo = unpack2(acc[i][0]);   // col n,   rows (2i, 2i+1)
            float2 hi = unpack2(acc[i][1]);   // col n+1, rows (2i, 2i+1)
            size_t r0 = (size_t)(m0 + mbase + 2*i);
            *(float2*)&outp[r0*G4 + n]     = make_float2(lo.x + bn0, hi.x + bn1);
            *(float2*)&outp[(r0+1)*G4 + n] = make_float2(lo.y + bn0, hi.y + bn1);
        }
    }
}

// ---------------- K3: LSTM recurrence (prefetched xw) ----------------
#define LSTM_SMEM_FLOATS (40000 + 104 + 104 + 800)
#define LSTM_SMEM_BYTES  (LSTM_SMEM_FLOATS * 4)

__global__ void k_lstm(const float* __restrict__ whh_f, const float* __restrict__ whh_b)
{
    extern __shared__ float sm[];
    float* whh_s = sm;            // 40000 floats (k-major [100][400])
    float* h0    = sm + 40000;
    float* h1    = sm + 40104;
    float* gate  = sm + 40208;    // 2 * 400

    int t   = threadIdx.x;        // 0..199
    int dir = blockIdx.x >> 6;
    int b0  = (blockIdx.x & 63) * 2;

    const float* whh = dir ? whh_b : whh_f;
    const float* xw  = g_xw[dir];

    for (int idx = t; idx < 40000; idx += 200) {
        int r = idx / HH, k = idx % HH;
        whh_s[k*G4 + r] = whh[idx];
    }
    if (t < HH) { h0[t] = 0.0f; h1[t] = 0.0f; }
    float c_reg = 0.0f;
    int r_act = t / HH;
    int j_act = t - r_act*HH;
    __syncthreads();

    int g = 2*t;
    const float4* h0f = (const float4*)h0;
    const float4* h1f = (const float4*)h1;

    int s0 = dir ? (SS-1) : 0;
    float2 nx0 = *(const float2*)(xw + ((size_t)b0    *SS + s0)*G4 + g);
    float2 nx1 = *(const float2*)(xw + ((size_t)(b0+1)*SS + s0)*G4 + g);

    for (int step = 0; step < SS; step++) {
        int sidx = dir ? (SS-1-step) : step;
        float a00 = nx0.x, a10 = nx0.y, a01 = nx1.x, a11 = nx1.y;
        if (step + 1 < SS) {
            int snext = dir ? (SS-2-step) : (step+1);
            nx0 = *(const float2*)(xw + ((size_t)b0    *SS + snext)*G4 + g);
            nx1 = *(const float2*)(xw + ((size_t)(b0+1)*SS + snext)*G4 + g);
        }

        #pragma unroll
        for (int k4 = 0; k4 < 25; k4++) {
            float4 hv0 = h0f[k4];
            float4 hv1 = h1f[k4];
            float2 w0 = *(const float2*)&whh_s[(k4*4+0)*G4 + g];
            a00 += w0.x*hv0.x; a10 += w0.y*hv0.x; a01 += w0.x*hv1.x; a11 += w0.y*hv1.x;
            float2 w1 = *(const float2*)&whh_s[(k4*4+1)*G4 + g];
            a00 += w1.x*hv0.y; a10 += w1.y*hv0.y; a01 += w1.x*hv1.y; a11 += w1.y*hv1.y;
            float2 w2 = *(const float2*)&whh_s[(k4*4+2)*G4 + g];
            a00 += w2.x*hv0.z; a10 += w2.y*hv0.z; a01 += w2.x*hv1.z; a11 += w2.y*hv1.z;
            float2 w3 = *(const float2*)&whh_s[(k4*4+3)*G4 + g];
            a00 += w3.x*hv0.w; a10 += w3.y*hv0.w; a01 += w3.x*hv1.w; a11 += w3.y*hv1.w;
        }
        *(float2*)&gate[g]       = make_float2(a00, a10);
        *(float2*)&gate[G4 + g]  = make_float2(a01, a11);
        __syncthreads();

        {
            const float* gs = gate + r_act*G4;
            float gi = gs[j_act], gf = gs[HH + j_act], gg = gs[2*HH + j_act], go = gs[3*HH + j_act];
            float si = sigf(gi), sf = sigf(gf), so = sigf(go);
            c_reg = sf*c_reg + si*tanhf_fast(gg);
            float h = so*tanhf_fast(c_reg);
            ((r_act == 0) ? h0 : h1)[j_act] = h;
            g_hcat[((size_t)(b0 + r_act)*SS + sidx)*(2*HH) + dir*HH + j_act] = h;
        }
        __syncthreads();
    }
}

// ---------------- K4: emission = hcat(32768,200) @ proj_w^T(200,32) + proj_b ------
// 64-row tiles, BK=8, 256 threads, FFMA2 micro 8m x 1n.
__global__ void k_emission(const float* __restrict__ proj_w, const float* __restrict__ proj_b)
{
    __shared__ float As[8*68];
    __shared__ float Bs[8*32];
    int tid = threadIdx.x;
    int m0 = blockIdx.x * 64;
    int lr = tid >> 2;
    int lk = (tid & 3) * 2;
    int mbase = (tid >> 5) * 8;
    int n = tid & 31;

    ull acc[4] = {};

    for (int k0 = 0; k0 < 200; k0 += 8) {
        #pragma unroll
        for (int i = 0; i < 2; i++)
            As[(lk+i)*68 + lr] = g_hcat[(size_t)(m0+lr)*200 + k0 + lk + i];
        {
            int kq = tid >> 5, nn = tid & 31;
            Bs[kq*32 + nn] = proj_w[nn*200 + k0 + kq];
        }
        __syncthreads();
        #pragma unroll
        for (int kk = 0; kk < 8; kk++) {
            ulonglong2 aA = *(const ulonglong2*)&As[kk*68 + mbase];
            ulonglong2 aB = *(const ulonglong2*)&As[kk*68 + mbase + 4];
            ull s = splat2(Bs[kk*32 + n]);
            acc[0] = ffma2(aA.x, s, acc[0]);
            acc[1] = ffma2(aA.y, s, acc[1]);
            acc[2] = ffma2(aB.x, s, acc[2]);
            acc[3] = ffma2(aB.y, s, acc[3]);
        }
        __syncthreads();
    }

    float pb = proj_b[n];
    #pragma unroll
    for (int i = 0; i < 4; i++) {
        float2 v = unpack2(acc[i]);
        g_em[(size_t)(m0 + mbase + 2*i    )*TAGS + n] = v.x + pb;
        g_em[(size_t)(m0 + mbase + 2*i + 1)*TAGS + n] = v.y + pb;
    }
}

// ---------------- K5: CRF forward + gold score, one warp per batch row ----------------
__global__ void k_crf(const float* __restrict__ trans,
                      const int* __restrict__ y, const int* __restrict__ mask)
{
    int b = blockIdx.x;
    int j = threadIdx.x;

    float tr[32];
    #pragma unroll
    for (int i = 0; i < 32; i++) tr[i] = trans[i*TAGS + j];

    float la = (j == STARTT) ? 0.0f : NEGV;
    const float* em = g_em + (size_t)b*SS*TAGS;
    const int* mk = mask + b*SS;

    float e_next = em[j];
    int   m_next = mk[0];

    for (int s = 0; s < SS; s++) {
        float e = e_next;
        int mm = m_next;
        if (s + 1 < SS) {
            e_next = em[(s+1)*TAGS + j];
            m_next = mk[s+1];
        }
        float v[32];
        #pragma unroll
        for (int i = 0; i < 32; i++)
            v[i] = __shfl_sync(0xffffffffu, la, i) + tr[i];

        // tree max (depth 5)
        float mv[16];
        #pragma unroll
        for (int i = 0; i < 16; i++) mv[i] = fmaxf(v[i], v[i+16]);
        #pragma unroll
        for (int off = 8; off >= 1; off >>= 1)
            #pragma unroll
            for (int i = 0; i < off; i++) mv[i] = fmaxf(mv[i], mv[i+off]);
        float m = mv[0];

        float ev[32];
        #pragma unroll
        for (int i = 0; i < 32; i++) ev[i] = __expf(v[i] - m);
        #pragma unroll
        for (int off = 16; off >= 1; off >>= 1)
            #pragma unroll
            for (int i = 0; i < off; i++) ev[i] += ev[i+off];

        float la2 = e + m + __logf(ev[0]);
        la = mm ? la2 : la;
    }
    la += trans[j*TAGS + ENDT];

    float mv2 = la;
    #pragma unroll
    for (int o = 16; o > 0; o >>= 1) mv2 = fmaxf(mv2, __shfl_xor_sync(0xffffffffu, mv2, o));
    float ex = __expf(la - mv2);
    #pragma unroll
    for (int o = 16; o > 0; o >>= 1) ex += __shfl_xor_sync(0xffffffffu, ex, o);
    float total = mv2 + __logf(ex);

    const int* yb = y + b*SS;
    float sc = 0.0f;
    for (int s = j; s < SS; s += 32) {
        int cur  = yb[s];
        int prev = s ? yb[s-1] : STARTT;
        float p = em[s*TAGS + cur];
        float tt = trans[prev*TAGS + cur];
        sc += (p + tt) * (float)mk[s];
    }
    #pragma unroll
    for (int o = 16; o > 0; o >>= 1) sc += __shfl_xor_sync(0xffffffffu, sc, o);

    if (j == 0) {
        sc += trans[yb[SS-1]*TAGS + ENDT];
        g_res[b] = sc - total;
    }
}

// ---------------- K6: final reduction ----------------
__global__ void k_final(float* out)
{
    __shared__ float s[BB];
    int t = threadIdx.x;
    s[t] = g_res[t];
    __syncthreads();
    for (int o = 64; o > 0; o >>= 1) {
        if (t < o) s[t] += s[t+o];
        __syncthreads();
    }
    if (t == 0) out[0] = -s[0] / (float)BB;
}

// ---------------- launch ----------------
extern "C" void kernel_launch(void* const* d_in, const int* in_sizes, int n_in,
                              void* d_out, int out_size)
{
    const float* word_emb = (const float*)d_in[0];
    const float* char_emb = (const float*)d_in[1];
    const float* conv_w   = (const float*)d_in[2];
    const float* conv_b   = (const float*)d_in[3];
    const float* wih_f    = (const float*)d_in[4];
    const float* whh_f    = (const float*)d_in[5];
    const float* bih_f    = (const float*)d_in[6];
    const float* bhh_f    = (const float*)d_in[7];
    const float* wih_b    = (const float*)d_in[8];
    const float* whh_b    = (const float*)d_in[9];
    const float* bih_b    = (const float*)d_in[10];
    const float* bhh_b    = (const float*)d_in[11];
    const float* proj_w   = (const float*)d_in[12];
    const float* proj_b   = (const float*)d_in[13];
    const float* trans    = (const float*)d_in[14];
    const int*   word_x   = (const int*)d_in[15];
    const int*   char_x   = (const int*)d_in[16];
    const int*   y        = (const int*)d_in[17];
    const int*   mask     = (const int*)d_in[18];
    float* out = (float*)d_out;

    k_table<<<100, 90>>>(char_emb, conv_w);
    k_embed<<<BB*SS/8, 256>>>(word_emb, conv_b, word_x, char_x);

    dim3 g2(512, 7, 2);
    k_xw<<<g2, 256>>>(wih_f, bih_f, bhh_f, wih_b, bih_b, bhh_b);

    cudaFuncSetAttribute(k_lstm, cudaFuncAttributeMaxDynamicSharedMemorySize, LSTM_SMEM_BYTES);
    k_lstm<<<128, 200, LSTM_SMEM_BYTES>>>(whh_f, whh_b);

    k_emission<<<BB*SS/64, 256>>>(proj_w, proj_b);

    k_crf<<<BB, 32>>>(trans, y, mask);

    k_final<<<1, BB>>>(out);
}

// round 4
// speedup vs baseline: 2.3999x; 1.2710x over previous
#include <cuda_runtime.h>
#include <math.h>

// ---------------- problem constants ----------------
#define BB    128
#define SS    256
#define LLQ   10
#define TAGS  32
#define STARTT 30
#define ENDT   31
#define WDIM  100
#define CDIM  30
#define FILT  30
#define HH    100
#define LSTM_IN 130
#define G4    400
#define NEGV  (-10000.0f)

typedef unsigned long long ull;

// ---------------- scratch ----------------
__device__ float g_T  [100*3*FILT];            // conv table T[c][k][f]
__device__ float g_x  [BB*SS*LSTM_IN];         // concat(word_emb, char_feat)
__device__ float g_xw [2][BB*SS*G4];           // x @ wih^T + b, per dir
__device__ float g_hcat[BB*SS*2*HH];           // [token][dir*100+j]
__device__ float g_em [BB*SS*TAGS];            // emission
__device__ float g_res[BB];

// ---------------- helpers ----------------
__device__ __forceinline__ float sigf(float x) {
    return __fdividef(1.0f, 1.0f + __expf(-x));
}
__device__ __forceinline__ float tanhf_fast(float x) {
    float e = __expf(-2.0f * fabsf(x));
    float t = __fdividef(1.0f - e, 1.0f + e);
    return copysignf(t, x);
}
__device__ __forceinline__ ull ffma2(ull a, ull b, ull c) {
    ull d;
    asm("fma.rn.f32x2 %0, %1, %2, %3;" : "=l"(d) : "l"(a), "l"(b), "l"(c));
    return d;
}
__device__ __forceinline__ ull splat2(float x) {
    ull d; asm("mov.b64 %0, {%1, %1};" : "=l"(d) : "f"(x)); return d;
}
__device__ __forceinline__ ull pack2(float lo, float hi) {
    ull d; asm("mov.b64 %0, {%1, %2};" : "=l"(d) : "f"(lo), "f"(hi)); return d;
}
__device__ __forceinline__ float2 unpack2(ull v) {
    float2 r; asm("mov.b64 {%0, %1}, %2;" : "=f"(r.x), "=f"(r.y) : "l"(v)); return r;
}

// ---------------- K0: conv table T[c][k][f] = dot(char_emb[c], conv_w[f,k,:]) ----
__global__ void k_table(const float* __restrict__ char_emb,
                        const float* __restrict__ conv_w)
{
    __shared__ float ce[CDIM];
    int c = blockIdx.x;
    int t = threadIdx.x;       // 0..89
    if (t < CDIM) ce[t] = char_emb[c*CDIM + t];
    __syncthreads();
    int k = t / FILT, f = t % FILT;
    float s = 0.0f;
    #pragma unroll
    for (int d = 0; d < CDIM; d++) s += ce[d] * conv_w[f*90 + k*CDIM + d];
    g_T[c*90 + k*FILT + f] = s;
}

// ---------------- K1: word-emb gather + char maxpool (table lookup) ----------------
__global__ void k_embed(const float* __restrict__ word_emb,
                        const float* __restrict__ conv_b,
                        const int*   __restrict__ word_x,
                        const int*   __restrict__ char_x)
{
    __shared__ float ts[9000];
    int tid = threadIdx.x;
    for (int i = tid; i < 9000; i += 256) ts[i] = g_T[i];
    __syncthreads();

    int lane = tid & 31;
    int token = blockIdx.x * 8 + (tid >> 5);

    int w = word_x[token];
    for (int i = lane; i < WDIM; i += 32)
        g_x[(size_t)token*LSTM_IN + i] = word_emb[(size_t)w*WDIM + i];

    int cval = (lane < LLQ) ? char_x[(size_t)token*LLQ + lane] : 0;
    int f2 = (lane < FILT) ? lane : 0;

    float best = -1e30f;
    #pragma unroll
    for (int p = 0; p < 12; p++) {
        float s = 0.0f;
        #pragma unroll
        for (int k = 0; k < 3; k++) {
            int q = p + k - 2;
            if (q >= 0 && q < LLQ) {
                int cq = __shfl_sync(0xffffffffu, cval, q);
                s += ts[cq*90 + k*FILT + f2];
            }
        }
        best = fmaxf(best, s);
    }
    if (lane < FILT)
        g_x[(size_t)token*LSTM_IN + WDIM + lane] = best + conv_b[lane];
}

// ---------------- K2: xw = x(32768,130) @ wih^T(130,400) + (bih+bhh) ----------------
__global__ void k_xw(const float* __restrict__ wih_f, const float* __restrict__ bih_f, const float* __restrict__ bhh_f,
                     const float* __restrict__ wih_b, const float* __restrict__ bih_b, const float* __restrict__ bhh_b)
{
    int dir = blockIdx.z;
    const float* wih = dir ? wih_b : wih_f;
    const float* bih = dir ? bih_b : bih_f;
    const float* bhh = dir ? bhh_b : bhh_f;
    float* outp = g_xw[dir];

    __shared__ float As[16*68];
    __shared__ float Bs[16*68];

    int m0 = blockIdx.x * 64;
    int n0 = blockIdx.y * 64;
    int tid = threadIdx.x;
    int lr = tid >> 2;
    int lk = (tid & 3) * 4;
    int mbase = (tid >> 5) * 8;
    int nb = (tid & 31) * 2;

    ull acc[4][2] = {};

    for (int k0 = 0; k0 < 144; k0 += 16) {
        #pragma unroll
        for (int i = 0; i < 4; i++) {
            int k = k0 + lk + i;
            As[(lk+i)*68 + lr] = (k < LSTM_IN) ? g_x[(size_t)(m0+lr)*LSTM_IN + k] : 0.0f;
            Bs[(lk+i)*68 + lr] = (k < LSTM_IN && (n0+lr) < G4) ? wih[(size_t)(n0+lr)*LSTM_IN + k] : 0.0f;
        }
        __syncthreads();
        #pragma unroll
        for (int kk = 0; kk < 16; kk++) {
            ulonglong2 aA = *(const ulonglong2*)&As[kk*68 + mbase];
            ulonglong2 aB = *(const ulonglong2*)&As[kk*68 + mbase + 4];
            float2 bv = *(const float2*)&Bs[kk*68 + nb];
            ull s0 = splat2(bv.x), s1 = splat2(bv.y);
            acc[0][0] = ffma2(aA.x, s0, acc[0][0]); acc[0][1] = ffma2(aA.x, s1, acc[0][1]);
            acc[1][0] = ffma2(aA.y, s0, acc[1][0]); acc[1][1] = ffma2(aA.y, s1, acc[1][1]);
            acc[2][0] = ffma2(aB.x, s0, acc[2][0]); acc[2][1] = ffma2(aB.x, s1, acc[2][1]);
            acc[3][0] = ffma2(aB.y, s0, acc[3][0]); acc[3][1] = ffma2(aB.y, s1, acc[3][1]);
        }
        __syncthreads();
    }

    int n = n0 + nb;
    if (n < G4) {
        float bn0 = bih[n] + bhh[n];
        float bn1 = bih[n+1] + bhh[n+1];
        #pragma unroll
        for (int i = 0; i < 4; i++) {
            float2 lo = unpack2(acc[i][0]);
            float2 hi = unpack2(acc[i][1]);
            size_t r0 = (size_t)(m0 + mbase + 2*i);
            *(float2*)&outp[r0*G4 + n]     = make_float2(lo.x + bn0, hi.x + bn1);
            *(float2*)&outp[(r0+1)*G4 + n] = make_float2(lo.y + bn0, hi.y + bn1);
        }
    }
}

// ---------------- K3: LSTM recurrence — whh in registers, FFMA2 k-pairs ----------------
// 128 blocks (2 dir x 64 batch-pairs), 400 threads. Thread t = gate row g.
// whh row (100 floats) lives in 50 ull registers as (k even, k odd) pairs.
// FFMA2 lanes carry even-k / odd-k partial sums; one horizontal add per gate.
__global__ void __launch_bounds__(400, 1) k_lstm(const float* __restrict__ whh_f,
                                                 const float* __restrict__ whh_b)
{
    __shared__ __align__(16) float h0[HH];
    __shared__ __align__(16) float h1[HH];
    __shared__ float gate[2*G4];

    int t   = threadIdx.x;        // 0..399 = gate row
    int dir = blockIdx.x >> 6;
    int b0  = (blockIdx.x & 63) * 2;

    const float* whh = dir ? whh_b : whh_f;
    const float* xw  = g_xw[dir];

    // load whh row t into registers: 25 x LDG.128
    ull w[50];
    {
        const ulonglong2* row = (const ulonglong2*)(whh + (size_t)t*HH);
        #pragma unroll
        for (int i = 0; i < 25; i++) {
            ulonglong2 v = row[i];
            w[2*i]   = v.x;
            w[2*i+1] = v.y;
        }
    }

    if (t < HH) { h0[t] = 0.0f; h1[t] = 0.0f; }
    int r_act = (t < 200) ? (t / HH) : 0;     // batch row for activation phase
    int j_act = (t < 200) ? (t % HH) : 0;
    float c_reg = 0.0f;
    __syncthreads();

    const ulonglong2* hp0 = (const ulonglong2*)h0;   // 4 floats per load
    const ulonglong2* hp1 = (const ulonglong2*)h1;

    int s0 = dir ? (SS-1) : 0;
    float xa = xw[((size_t)b0    *SS + s0)*G4 + t];
    float xb = xw[((size_t)(b0+1)*SS + s0)*G4 + t];

    for (int step = 0; step < SS; step++) {
        int sidx = dir ? (SS-1-step) : step;

        ull acc00 = pack2(xa, 0.0f), acc01 = 0ULL;   // batch b0: even/odd chains
        ull acc10 = pack2(xb, 0.0f), acc11 = 0ULL;   // batch b0+1
        #pragma unroll
        for (int i = 0; i < 25; i++) {
            ulonglong2 hv0 = hp0[i];
            ulonglong2 hv1 = hp1[i];
            acc00 = ffma2(w[2*i],   hv0.x, acc00);
            acc01 = ffma2(w[2*i+1], hv0.y, acc01);
            acc10 = ffma2(w[2*i],   hv1.x, acc10);
            acc11 = ffma2(w[2*i+1], hv1.y, acc11);
        }
        // prefetch next step's xw while gates settle
        if (step + 1 < SS) {
            int snext = dir ? (SS-2-step) : (step+1);
            xa = xw[((size_t)b0    *SS + snext)*G4 + t];
            xb = xw[((size_t)(b0+1)*SS + snext)*G4 + t];
        }

        float2 p0 = unpack2(acc00), q0 = unpack2(acc01);
        float2 p1 = unpack2(acc10), q1 = unpack2(acc11);
        gate[t]      = (p0.x + q0.x) + (p0.y + q0.y);
        gate[G4 + t] = (p1.x + q1.x) + (p1.y + q1.y);
        __syncthreads();

        if (t < 200) {
            const float* gs = gate + r_act*G4;
            float gi = gs[j_act], gf = gs[HH + j_act], gg = gs[2*HH + j_act], go = gs[3*HH + j_act];
            float si = sigf(gi), sf = sigf(gf), so = sigf(go);
            c_reg = sf*c_reg + si*tanhf_fast(gg);
            float h = so*tanhf_fast(c_reg);
            ((r_act == 0) ? h0 : h1)[j_act] = h;
            g_hcat[((size_t)(b0 + r_act)*SS + sidx)*(2*HH) + dir*HH + j_act] = h;
        }
        __syncthreads();
    }
}

// ---------------- K4: emission = hcat(32768,200) @ proj_w^T(200,32) + proj_b ------
__global__ void k_emission(const float* __restrict__ proj_w, const float* __restrict__ proj_b)
{
    __shared__ float As[8*68];
    __shared__ float Bs[8*32];
    int tid = threadIdx.x;
    int m0 = blockIdx.x * 64;
    int lr = tid >> 2;
    int lk = (tid & 3) * 2;
    int mbase = (tid >> 5) * 8;
    int n = tid & 31;

    ull acc[4] = {};

    for (int k0 = 0; k0 < 200; k0 += 8) {
        #pragma unroll
        for (int i = 0; i < 2; i++)
            As[(lk+i)*68 + lr] = g_hcat[(size_t)(m0+lr)*200 + k0 + lk + i];
        {
            int kq = tid >> 5, nn = tid & 31;
            Bs[kq*32 + nn] = proj_w[nn*200 + k0 + kq];
        }
        __syncthreads();
        #pragma unroll
        for (int kk = 0; kk < 8; kk++) {
            ulonglong2 aA = *(const ulonglong2*)&As[kk*68 + mbase];
            ulonglong2 aB = *(const ulonglong2*)&As[kk*68 + mbase + 4];
            ull s = splat2(Bs[kk*32 + n]);
            acc[0] = ffma2(aA.x, s, acc[0]);
            acc[1] = ffma2(aA.y, s, acc[1]);
            acc[2] = ffma2(aB.x, s, acc[2]);
            acc[3] = ffma2(aB.y, s, acc[3]);
        }
        __syncthreads();
    }

    float pb = proj_b[n];
    #pragma unroll
    for (int i = 0; i < 4; i++) {
        float2 v = unpack2(acc[i]);
        g_em[(size_t)(m0 + mbase + 2*i    )*TAGS + n] = v.x + pb;
        g_em[(size_t)(m0 + mbase + 2*i + 1)*TAGS + n] = v.y + pb;
    }
}

// ---------------- K5: CRF forward + gold score, one warp per batch row ----------------
__global__ void k_crf(const float* __restrict__ trans,
                      const int* __restrict__ y, const int* __restrict__ mask)
{
    int b = blockIdx.x;
    int j = threadIdx.x;

    float tr[32];
    #pragma unroll
    for (int i = 0; i < 32; i++) tr[i] = trans[i*TAGS + j];

    float la = (j == STARTT) ? 0.0f : NEGV;
    const float* em = g_em + (size_t)b*SS*TAGS;
    const int* mk = mask + b*SS;

    float e_next = em[j];
    int   m_next = mk[0];

    for (int s = 0; s < SS; s++) {
        float e = e_next;
        int mm = m_next;
        if (s + 1 < SS) {
            e_next = em[(s+1)*TAGS + j];
            m_next = mk[s+1];
        }
        float v[32];
        #pragma unroll
        for (int i = 0; i < 32; i++)
            v[i] = __shfl_sync(0xffffffffu, la, i) + tr[i];

        float mv[16];
        #pragma unroll
        for (int i = 0; i < 16; i++) mv[i] = fmaxf(v[i], v[i+16]);
        #pragma unroll
        for (int off = 8; off >= 1; off >>= 1)
            #pragma unroll
            for (int i = 0; i < off; i++) mv[i] = fmaxf(mv[i], mv[i+off]);
        float m = mv[0];

        float ev[32];
        #pragma unroll
        for (int i = 0; i < 32; i++) ev[i] = __expf(v[i] - m);
        #pragma unroll
        for (int off = 16; off >= 1; off >>= 1)
            #pragma unroll
            for (int i = 0; i < off; i++) ev[i] += ev[i+off];

        float la2 = e + m + __logf(ev[0]);
        la = mm ? la2 : la;
    }
    la += trans[j*TAGS + ENDT];

    float mv2 = la;
    #pragma unroll
    for (int o = 16; o > 0; o >>= 1) mv2 = fmaxf(mv2, __shfl_xor_sync(0xffffffffu, mv2, o));
    float ex = __expf(la - mv2);
    #pragma unroll
    for (int o = 16; o > 0; o >>= 1) ex += __shfl_xor_sync(0xffffffffu, ex, o);
    float total = mv2 + __logf(ex);

    const int* yb = y + b*SS;
    float sc = 0.0f;
    for (int s = j; s < SS; s += 32) {
        int cur  = yb[s];
        int prev = s ? yb[s-1] : STARTT;
        float p = em[s*TAGS + cur];
        float tt = trans[prev*TAGS + cur];
        sc += (p + tt) * (float)mk[s];
    }
    #pragma unroll
    for (int o = 16; o > 0; o >>= 1) sc += __shfl_xor_sync(0xffffffffu, sc, o);

    if (j == 0) {
        sc += trans[yb[SS-1]*TAGS + ENDT];
        g_res[b] = sc - total;
    }
}

// ---------------- K6: final reduction ----------------
__global__ void k_final(float* out)
{
    __shared__ float s[BB];
    int t = threadIdx.x;
    s[t] = g_res[t];
    __syncthreads();
    for (int o = 64; o > 0; o >>= 1) {
        if (t < o) s[t] += s[t+o];
        __syncthreads();
    }
    if (t == 0) out[0] = -s[0] / (float)BB;
}

// ---------------- launch ----------------
extern "C" void kernel_launch(void* const* d_in, const int* in_sizes, int n_in,
                              void* d_out, int out_size)
{
    const float* word_emb = (const float*)d_in[0];
    const float* char_emb = (const float*)d_in[1];
    const float* conv_w   = (const float*)d_in[2];
    const float* conv_b   = (const float*)d_in[3];
    const float* wih_f    = (const float*)d_in[4];
    const float* whh_f    = (const float*)d_in[5];
    const float* bih_f    = (const float*)d_in[6];
    const float* bhh_f    = (const float*)d_in[7];
    const float* wih_b    = (const float*)d_in[8];
    const float* whh_b    = (const float*)d_in[9];
    const float* bih_b    = (const float*)d_in[10];
    const float* bhh_b    = (const float*)d_in[11];
    const float* proj_w   = (const float*)d_in[12];
    const float* proj_b   = (const float*)d_in[13];
    const float* trans    = (const float*)d_in[14];
    const int*   word_x   = (const int*)d_in[15];
    const int*   char_x   = (const int*)d_in[16];
    const int*   y        = (const int*)d_in[17];
    const int*   mask     = (const int*)d_in[18];
    float* out = (float*)d_out;

    k_table<<<100, 90>>>(char_emb, conv_w);
    k_embed<<<BB*SS/8, 256>>>(word_emb, conv_b, word_x, char_x);

    dim3 g2(512, 7, 2);
    k_xw<<<g2, 256>>>(wih_f, bih_f, bhh_f, wih_b, bih_b, bhh_b);

    k_lstm<<<128, 400>>>(whh_f, whh_b);

    k_emission<<<BB*SS/64, 256>>>(proj_w, proj_b);

    k_crf<<<BB, 32>>>(trans, y, mask);

    k_final<<<1, BB>>>(out);
}